// round 1
// baseline (speedup 1.0000x reference)
#include <cuda_runtime.h>
#include <cstdint>

#define N_NODES 10000
#define N_EDGES 320000
#define CH 64
#define TE 128          // edges per block in MLP kernel

// ---------------- scratch (device globals; allocation-free) ----------------
__device__ float g_h[N_NODES * CH];                 // 2.56 MB
__device__ float g_w[(size_t)N_EDGES * 192];        // 245.8 MB: radial weights per (edge, l, c)
__device__ float g_sh[(size_t)N_EDGES * 12];        // 15.4 MB: sh padded to 12
__device__ float g_agg[(size_t)N_NODES * 9 * 64];   // 23 MB: [n][k][c]
__device__ int   g_count[N_NODES];
__device__ int   g_rowstart[N_NODES + 1];
__device__ int   g_cursor[N_NODES];
__device__ int   g_csr[N_EDGES];

__device__ __forceinline__ float silu_f(float x) {
    return x / (1.f + __expf(-x));
}

// ---------------- h = (node_feats @ W_up) / 8 ----------------
__global__ __launch_bounds__(256) void k_h(const float* __restrict__ nf,
                                           const float* __restrict__ Wup) {
    __shared__ float sW[64 * 64];
    __shared__ float sN[4 * 64];
    int t = threadIdx.x;
    for (int idx = t; idx < 1024; idx += 256)
        ((float4*)sW)[idx] = ((const float4*)Wup)[idx];
    int n0 = blockIdx.x * 4;
    if (t < 64)
        ((float4*)sN)[t] = ((const float4*)(nf + (size_t)n0 * 64))[t];
    __syncthreads();
    int i = t >> 6, c = t & 63;
    float a0 = 0.f, a1 = 0.f;
#pragma unroll
    for (int k = 0; k < 64; k += 2) {
        a0 = fmaf(sN[i * 64 + k],     sW[k * 64 + c],       a0);
        a1 = fmaf(sN[i * 64 + k + 1], sW[(k + 1) * 64 + c], a1);
    }
    g_h[(size_t)(n0 + i) * 64 + c] = (a0 + a1) * 0.125f;
}

// ---------------- fused radial MLP + spherical harmonics ----------------
template <int K>
__device__ __forceinline__ void gemm_tile(const float* __restrict__ sIn,
                                          const float* __restrict__ sW,
                                          float acc[8][4], int e0, int j0) {
#pragma unroll 8
    for (int k = 0; k < K; ++k) {
        float4 w = *(const float4*)(sW + k * 64 + j0);
#pragma unroll
        for (int i = 0; i < 8; ++i) {
            float a = sIn[(e0 + i) * 68 + k];
            acc[i][0] = fmaf(a, w.x, acc[i][0]);
            acc[i][1] = fmaf(a, w.y, acc[i][1]);
            acc[i][2] = fmaf(a, w.z, acc[i][2]);
            acc[i][3] = fmaf(a, w.w, acc[i][3]);
        }
    }
}

__device__ __forceinline__ void zero_acc(float acc[8][4]) {
#pragma unroll
    for (int i = 0; i < 8; ++i) {
        acc[i][0] = 0.f; acc[i][1] = 0.f; acc[i][2] = 0.f; acc[i][3] = 0.f;
    }
}

__device__ __forceinline__ void store_act(float* __restrict__ sOut, int e0, int j0,
                                          float acc[8][4], float scale) {
#pragma unroll
    for (int i = 0; i < 8; ++i) {
        float4 v;
        v.x = silu_f(acc[i][0] * scale);
        v.y = silu_f(acc[i][1] * scale);
        v.z = silu_f(acc[i][2] * scale);
        v.w = silu_f(acc[i][3] * scale);
        *(float4*)(sOut + (e0 + i) * 68 + j0) = v;
    }
}

__device__ __forceinline__ void load_w64(float* __restrict__ sW,
                                         const float* __restrict__ gW, int t) {
    for (int idx = t; idx < 1024; idx += 256)
        ((float4*)sW)[idx] = ((const float4*)gW)[idx];
}

__global__ __launch_bounds__(256) void k_edge(const float* __restrict__ evec,
                                              const float* __restrict__ rad,
                                              const float* __restrict__ W1,
                                              const float* __restrict__ W2,
                                              const float* __restrict__ W3,
                                              const float* __restrict__ W4) {
    extern __shared__ float sm[];
    float* sA = sm;                  // [128][68]
    float* sB = sm + 128 * 68;       // [128][68]
    float* sW = sm + 2 * 128 * 68;   // [64][64]
    int t = threadIdx.x;
    int e_base = blockIdx.x * TE;

    // spherical harmonics (threads 0..127, one edge each)
    if (t < TE) {
        int e = e_base + t;
        float x = evec[(size_t)e * 3], y = evec[(size_t)e * 3 + 1], z = evec[(size_t)e * 3 + 2];
        float rn = rsqrtf(x * x + y * y + z * z);
        x *= rn; y *= rn; z *= rn;
        const float c3  = 1.7320508075688772f;
        const float c15 = 3.872983346207417f;
        const float c5h = 1.118033988749895f;    // 0.5*sqrt(5)
        const float c15h= 1.9364916731037085f;   // 0.5*sqrt(15)
        float* o = g_sh + (size_t)e * 12;
        o[0] = 1.f;
        o[1] = c3 * x; o[2] = c3 * y; o[3] = c3 * z;
        o[4] = c15 * x * y; o[5] = c15 * y * z;
        o[6] = c5h * (3.f * z * z - 1.f);
        o[7] = c15 * x * z; o[8] = c15h * (x * x - y * y);
    }

    // load radial [128][8] -> sA (edge-major, pad 68)
    {
        int e = t >> 1, half = t & 1;
        float4 r = *(const float4*)(rad + (size_t)(e_base + e) * 8 + half * 4);
        float* dst = sA + e * 68 + half * 4;
        dst[0] = r.x; dst[1] = r.y; dst[2] = r.z; dst[3] = r.w;
    }
    if (t < 128) ((float4*)sW)[t] = ((const float4*)W1)[t];   // W1: 8x64
    __syncthreads();

    int tx = t & 15, ty = t >> 4;
    int e0 = ty * 8, j0 = tx * 4;
    float acc[8][4];

    // L1: [128,8]@[8,64]
    zero_acc(acc);
    gemm_tile<8>(sA, sW, acc, e0, j0);
    store_act(sB, e0, j0, acc, 0.35355339059327373f);   // 1/sqrt(8)
    __syncthreads();

    // L2
    load_w64(sW, W2, t);
    __syncthreads();
    zero_acc(acc);
    gemm_tile<64>(sB, sW, acc, e0, j0);
    store_act(sA, e0, j0, acc, 0.125f);
    __syncthreads();

    // L3
    load_w64(sW, W3, t);
    __syncthreads();
    zero_acc(acc);
    gemm_tile<64>(sA, sW, acc, e0, j0);
    store_act(sB, e0, j0, acc, 0.125f);
    __syncthreads();

    // L4: three 64-wide chunks of W4 [64][192], no silu, write to g_w
#pragma unroll 1
    for (int ch = 0; ch < 3; ++ch) {
        for (int idx = t; idx < 1024; idx += 256) {
            int k = idx >> 4, jj = (idx & 15) * 4;
            *(float4*)(sW + k * 64 + jj) =
                *(const float4*)(W4 + (size_t)k * 192 + ch * 64 + jj);
        }
        __syncthreads();
        zero_acc(acc);
        gemm_tile<64>(sB, sW, acc, e0, j0);
#pragma unroll
        for (int i = 0; i < 8; ++i) {
            float4 v = make_float4(acc[i][0] * 0.125f, acc[i][1] * 0.125f,
                                   acc[i][2] * 0.125f, acc[i][3] * 0.125f);
            *(float4*)(g_w + (size_t)(e_base + e0 + i) * 192 + ch * 64 + j0) = v;
        }
        __syncthreads();
    }
}

// ---------------- CSR build ----------------
__global__ void k_zero() {
    int i = blockIdx.x * blockDim.x + threadIdx.x;
    if (i < N_NODES) g_count[i] = 0;
}

__global__ void k_count(const int* __restrict__ recv) {
    int e = blockIdx.x * blockDim.x + threadIdx.x;
    if (e < N_EDGES) atomicAdd(&g_count[recv[e]], 1);
}

__global__ __launch_bounds__(256) void k_scan() {
    __shared__ int part[256];
    int t = threadIdx.x;
    int base = t * 40;
    int s = 0;
    for (int i = 0; i < 40; ++i) {
        int idx = base + i;
        if (idx < N_NODES) s += g_count[idx];
    }
    part[t] = s;
    __syncthreads();
    if (t == 0) {
        int run = 0;
        for (int i = 0; i < 256; ++i) { int v = part[i]; part[i] = run; run += v; }
    }
    __syncthreads();
    int run = part[t];
    for (int i = 0; i < 40; ++i) {
        int idx = base + i;
        if (idx < N_NODES) {
            g_rowstart[idx] = run;
            g_cursor[idx] = run;
            run += g_count[idx];
        }
    }
    if (t == 255) g_rowstart[N_NODES] = run;
}

__global__ void k_fill(const int* __restrict__ recv) {
    int e = blockIdx.x * blockDim.x + threadIdx.x;
    if (e < N_EDGES) {
        int r = recv[e];
        int pos = atomicAdd(&g_cursor[r], 1);
        g_csr[pos] = e;
    }
}

// ---------------- gather: per-node accumulation (no float atomics) ----------------
__global__ __launch_bounds__(256) void k_gather(const int* __restrict__ senders) {
    int t = threadIdx.x;
    int g = t >> 6, c = t & 63;
    int n = blockIdx.x * 4 + g;
    int beg = g_rowstart[n], end = g_rowstart[n + 1];
    float a0 = 0.f, a1 = 0.f, a2 = 0.f, a3 = 0.f, a4 = 0.f,
          a5 = 0.f, a6 = 0.f, a7 = 0.f, a8 = 0.f;
    for (int p = beg; p < end; ++p) {
        int e = g_csr[p];
        int s = senders[e];
        float hv = g_h[(size_t)s * 64 + c];
        const float* wp = g_w + (size_t)e * 192 + c;
        float w0 = wp[0], w1 = wp[64], w2 = wp[128];
        const float* shp = g_sh + (size_t)e * 12;
        float4 s0 = *(const float4*)shp;        // [1, sh1x, sh1y, sh1z]
        float4 s1 = *(const float4*)(shp + 4);  // [sh2_0..3]
        float s8 = shp[8];
        float hw0 = hv * w0, hw1 = hv * w1, hw2 = hv * w2;
        a0 += hw0;                 // Y00 == 1
        a1 = fmaf(hw1, s0.y, a1);
        a2 = fmaf(hw1, s0.z, a2);
        a3 = fmaf(hw1, s0.w, a3);
        a4 = fmaf(hw2, s1.x, a4);
        a5 = fmaf(hw2, s1.y, a5);
        a6 = fmaf(hw2, s1.z, a6);
        a7 = fmaf(hw2, s1.w, a7);
        a8 = fmaf(hw2, s8,   a8);
    }
    const float inv_avg = 1.f / 32.f;
    float* ag = g_agg + (size_t)n * 576 + c;
    ag[0]       = a0 * inv_avg;
    ag[64]      = a1 * inv_avg;
    ag[2 * 64]  = a2 * inv_avg;
    ag[3 * 64]  = a3 * inv_avg;
    ag[4 * 64]  = a4 * inv_avg;
    ag[5 * 64]  = a5 * inv_avg;
    ag[6 * 64]  = a6 * inv_avg;
    ag[7 * 64]  = a7 * inv_avg;
    ag[8 * 64]  = a8 * inv_avg;
}

// ---------------- linear_down ----------------
template <int D, int KOFF, int OFF>
__device__ __forceinline__ void down_part(const float* __restrict__ sAg,
                                          const float* __restrict__ wrow,
                                          float* __restrict__ outn, int dch) {
    float acc[D];
#pragma unroll
    for (int m = 0; m < D; ++m) acc[m] = 0.f;
#pragma unroll
    for (int c4 = 0; c4 < 16; ++c4) {
        float4 w = *(const float4*)(wrow + c4 * 4);
#pragma unroll
        for (int m = 0; m < D; ++m) {
            float4 a = *(const float4*)(sAg + (KOFF + m) * 64 + c4 * 4);
            acc[m] += a.x * w.x + a.y * w.y + a.z * w.z + a.w * w.w;
        }
    }
#pragma unroll
    for (int m = 0; m < D; ++m)
        outn[OFF + dch * D + m] = acc[m] * 0.125f;
}

__global__ __launch_bounds__(256) void k_down(const float* __restrict__ Wd,
                                              float* __restrict__ out) {
    extern __shared__ float sm[];
    float* sWt = sm;                 // [192][68]  (l*64+dch major, c minor, padded)
    float* sAg = sm + 192 * 68;      // [9*64]
    int t = threadIdx.x;
    // transpose-load W_down: sWt[(l*64+dch)*68 + c] = Wd[l*4096 + c*64 + dch]
    for (int idx = t; idx < 3 * 4096; idx += 256) {
        int l = idx >> 12, rem = idx & 4095, c = rem >> 6, dch = rem & 63;
        sWt[(l * 64 + dch) * 68 + c] = Wd[idx];
    }
    __syncthreads();
    int nb = blockIdx.x * 8;
    for (int i = 0; i < 8; ++i) {
        int n = nb + i;
        for (int idx = t; idx < 576; idx += 256)
            sAg[idx] = g_agg[(size_t)n * 576 + idx];
        __syncthreads();
        if (t < 192) {
            int l = t >> 6, dch = t & 63;
            float* outn = out + (size_t)n * 576;
            const float* wrow = sWt + t * 68;
            if (l == 0)      down_part<1, 0, 0>(sAg, wrow, outn, dch);
            else if (l == 1) down_part<3, 1, 64>(sAg, wrow, outn, dch);
            else             down_part<5, 4, 256>(sAg, wrow, outn, dch);
        }
        __syncthreads();
    }
}

// ---------------- launch ----------------
extern "C" void kernel_launch(void* const* d_in, const int* in_sizes, int n_in,
                              void* d_out, int out_size) {
    const float* evec = (const float*)d_in[0];
    const float* nf   = (const float*)d_in[1];
    const float* rad  = (const float*)d_in[2];
    const int* senders   = (const int*)d_in[3];
    const int* receivers = (const int*)d_in[4];
    const float* Wup = (const float*)d_in[5];
    const float* W1  = (const float*)d_in[6];
    const float* W2  = (const float*)d_in[7];
    const float* W3  = (const float*)d_in[8];
    const float* W4  = (const float*)d_in[9];
    const float* Wd  = (const float*)d_in[10];
    float* out = (float*)d_out;

    const int SMEM_EDGE = (2 * 128 * 68 + 64 * 64) * 4;   // 86016 B
    const int SMEM_DOWN = (192 * 68 + 9 * 64) * 4;        // 54528 B
    cudaFuncSetAttribute(k_edge, cudaFuncAttributeMaxDynamicSharedMemorySize, SMEM_EDGE);
    cudaFuncSetAttribute(k_down, cudaFuncAttributeMaxDynamicSharedMemorySize, SMEM_DOWN);

    k_zero<<<(N_NODES + 255) / 256, 256>>>();
    k_h<<<N_NODES / 4, 256>>>(nf, Wup);
    k_edge<<<N_EDGES / TE, 256, SMEM_EDGE>>>(evec, rad, W1, W2, W3, W4);
    k_count<<<N_EDGES / 256, 256>>>(receivers);
    k_scan<<<1, 256>>>();
    k_fill<<<N_EDGES / 256, 256>>>(receivers);
    k_gather<<<N_NODES / 4, 256>>>(senders);
    k_down<<<N_NODES / 8, 256, SMEM_DOWN>>>(Wd, out);
}

// round 2
// speedup vs baseline: 1.2298x; 1.2298x over previous
#include <cuda_runtime.h>
#include <cstdint>

#define N_NODES 10000
#define N_EDGES 320000
#define CH 64
#define TE 128          // edges per block in MLP kernel
#define AP 76           // activation smem pitch (conflict-free A-frag loads)
#define WP 68           // weight smem pitch (conflict-free B-frag loads)

// ---------------- scratch (device globals; allocation-free) ----------------
__device__ float g_h[N_NODES * CH];                 // 2.56 MB
__device__ float g_w[(size_t)N_EDGES * 192];        // 245.8 MB, CSR-pos order
__device__ float g_sh[(size_t)N_EDGES * 12];        // 15.4 MB, CSR-pos order
__device__ float g_agg[(size_t)N_NODES * 9 * 64];   // 23 MB: [n][k][c]
__device__ int   g_count[N_NODES];
__device__ int   g_rowstart[N_NODES + 1];
__device__ int   g_cursor[N_NODES];
__device__ int   g_csr[N_EDGES];                    // pos -> edge id
__device__ int   g_send[N_EDGES];                   // pos -> sender node

__device__ __forceinline__ float silu_f(float x) {
    return x / (1.f + __expf(-x));
}

__device__ __forceinline__ uint32_t f2tf32(float f) {
    uint32_t r;
    asm("cvt.rna.tf32.f32 %0, %1;" : "=r"(r) : "f"(f));
    return r;
}

__device__ __forceinline__ void mma_tf32(float acc[4], uint32_t a0, uint32_t a1,
                                         uint32_t a2, uint32_t a3,
                                         uint32_t b0, uint32_t b1) {
    asm volatile(
        "mma.sync.aligned.m16n8k8.row.col.f32.tf32.tf32.f32 "
        "{%0,%1,%2,%3}, {%4,%5,%6,%7}, {%8,%9}, {%0,%1,%2,%3};\n"
        : "+f"(acc[0]), "+f"(acc[1]), "+f"(acc[2]), "+f"(acc[3])
        : "r"(a0), "r"(a1), "r"(a2), "r"(a3), "r"(b0), "r"(b1));
}

// ---------------- h = (node_feats @ W_up) / 8 ----------------
__global__ __launch_bounds__(256) void k_h(const float* __restrict__ nf,
                                           const float* __restrict__ Wup) {
    __shared__ float sW[64 * 64];
    __shared__ float sN[4 * 64];
    int t = threadIdx.x;
    for (int idx = t; idx < 1024; idx += 256)
        ((float4*)sW)[idx] = ((const float4*)Wup)[idx];
    int n0 = blockIdx.x * 4;
    if (t < 64)
        ((float4*)sN)[t] = ((const float4*)(nf + (size_t)n0 * 64))[t];
    __syncthreads();
    int i = t >> 6, c = t & 63;
    float a0 = 0.f, a1 = 0.f;
#pragma unroll
    for (int k = 0; k < 64; k += 2) {
        a0 = fmaf(sN[i * 64 + k],     sW[k * 64 + c],       a0);
        a1 = fmaf(sN[i * 64 + k + 1], sW[(k + 1) * 64 + c], a1);
    }
    g_h[(size_t)(n0 + i) * 64 + c] = (a0 + a1) * 0.125f;
}

// ---------------- CSR build ----------------
__global__ void k_zero() {
    int i = blockIdx.x * blockDim.x + threadIdx.x;
    if (i < N_NODES) g_count[i] = 0;
}

__global__ void k_count(const int* __restrict__ recv) {
    int e = blockIdx.x * blockDim.x + threadIdx.x;
    if (e < N_EDGES) atomicAdd(&g_count[recv[e]], 1);
}

__global__ __launch_bounds__(256) void k_scan() {
    __shared__ int part[256];
    int t = threadIdx.x;
    int base = t * 40;
    int s = 0;
    for (int i = 0; i < 40; ++i) {
        int idx = base + i;
        if (idx < N_NODES) s += g_count[idx];
    }
    part[t] = s;
    __syncthreads();
    if (t == 0) {
        int run = 0;
        for (int i = 0; i < 256; ++i) { int v = part[i]; part[i] = run; run += v; }
    }
    __syncthreads();
    int run = part[t];
    for (int i = 0; i < 40; ++i) {
        int idx = base + i;
        if (idx < N_NODES) {
            g_rowstart[idx] = run;
            g_cursor[idx] = run;
            run += g_count[idx];
        }
    }
    if (t == 255) g_rowstart[N_NODES] = run;
}

__global__ void k_fill(const int* __restrict__ recv, const int* __restrict__ send) {
    int e = blockIdx.x * blockDim.x + threadIdx.x;
    if (e < N_EDGES) {
        int r = recv[e];
        int pos = atomicAdd(&g_cursor[r], 1);
        g_csr[pos] = e;
        g_send[pos] = send[e];
    }
}

// ---------------- fused radial MLP (tf32 mma) + spherical harmonics ----------------
// Block: 128 CSR positions, 256 threads = 8 warps. Warp w owns rows [16w, 16w+16).
// Activations live in smem as tf32 bit patterns, pitch AP=76.
// Weights transposed in smem: sW[n*WP + k], pitch WP=68.

__device__ __forceinline__ void load_w64(uint32_t* __restrict__ sW,
                                         const float* __restrict__ gW, int t) {
    for (int idx = t; idx < 4096; idx += 256) {
        int k = idx >> 6, n = idx & 63;
        sW[n * WP + k] = f2tf32(gW[idx]);
    }
}

template <int KSTEPS>
__device__ __forceinline__ void mma_layer(const uint32_t* __restrict__ sIn,
                                          const uint32_t* __restrict__ sW,
                                          float acc[8][4],
                                          int slab, int gid, int tid4) {
#pragma unroll
    for (int nt = 0; nt < 8; ++nt) {
        acc[nt][0] = 0.f; acc[nt][1] = 0.f; acc[nt][2] = 0.f; acc[nt][3] = 0.f;
    }
#pragma unroll
    for (int kk = 0; kk < KSTEPS; ++kk) {
        int c0 = kk * 8 + tid4;
        uint32_t a0 = sIn[(slab + gid) * AP + c0];
        uint32_t a1 = sIn[(slab + gid + 8) * AP + c0];
        uint32_t a2 = sIn[(slab + gid) * AP + c0 + 4];
        uint32_t a3 = sIn[(slab + gid + 8) * AP + c0 + 4];
#pragma unroll
        for (int nt = 0; nt < 8; ++nt) {
            uint32_t b0 = sW[(nt * 8 + gid) * WP + c0];
            uint32_t b1 = sW[(nt * 8 + gid) * WP + c0 + 4];
            mma_tf32(acc[nt], a0, a1, a2, a3, b0, b1);
        }
    }
}

__device__ __forceinline__ void store_act_mma(uint32_t* __restrict__ sOut,
                                              float acc[8][4], float scale,
                                              int slab, int gid, int tid4) {
#pragma unroll
    for (int nt = 0; nt < 8; ++nt) {
        int col = nt * 8 + 2 * tid4;
        uint32_t t0 = f2tf32(silu_f(acc[nt][0] * scale));
        uint32_t t1 = f2tf32(silu_f(acc[nt][1] * scale));
        uint32_t t2 = f2tf32(silu_f(acc[nt][2] * scale));
        uint32_t t3 = f2tf32(silu_f(acc[nt][3] * scale));
        *(uint2*)(sOut + (slab + gid) * AP + col)     = make_uint2(t0, t1);
        *(uint2*)(sOut + (slab + gid + 8) * AP + col) = make_uint2(t2, t3);
    }
}

__global__ __launch_bounds__(256) void k_edge(const float* __restrict__ evec,
                                              const float* __restrict__ rad,
                                              const float* __restrict__ W1,
                                              const float* __restrict__ W2,
                                              const float* __restrict__ W3,
                                              const float* __restrict__ W4) {
    extern __shared__ uint32_t sm[];
    uint32_t* sA = sm;                    // [128][AP]
    uint32_t* sB = sm + 128 * AP;         // [128][AP]
    uint32_t* sW = sm + 2 * 128 * AP;     // [64][WP]
    int t = threadIdx.x;
    int lane = t & 31, warp = t >> 5;
    int gid = lane >> 2, tid4 = lane & 3, slab = warp * 16;
    int pos_base = blockIdx.x * TE;

    // per-position: spherical harmonics + radial gather (CSR order)
    if (t < TE) {
        int pos = pos_base + t;
        int e = g_csr[pos];
        float x = evec[(size_t)e * 3], y = evec[(size_t)e * 3 + 1],
              z = evec[(size_t)e * 3 + 2];
        float rn = rsqrtf(x * x + y * y + z * z);
        x *= rn; y *= rn; z *= rn;
        const float c3  = 1.7320508075688772f;
        const float c15 = 3.872983346207417f;
        const float c5h = 1.118033988749895f;
        const float c15h= 1.9364916731037085f;
        float* o = g_sh + (size_t)pos * 12;
        o[0] = 1.f;
        o[1] = c3 * x; o[2] = c3 * y; o[3] = c3 * z;
        o[4] = c15 * x * y; o[5] = c15 * y * z;
        o[6] = c5h * (3.f * z * z - 1.f);
        o[7] = c15 * x * z; o[8] = c15h * (x * x - y * y);

        float4 r0 = *(const float4*)(rad + (size_t)e * 8);
        float4 r1 = *(const float4*)(rad + (size_t)e * 8 + 4);
        uint32_t* dst = sA + t * AP;
        dst[0] = f2tf32(r0.x); dst[1] = f2tf32(r0.y);
        dst[2] = f2tf32(r0.z); dst[3] = f2tf32(r0.w);
        dst[4] = f2tf32(r1.x); dst[5] = f2tf32(r1.y);
        dst[6] = f2tf32(r1.z); dst[7] = f2tf32(r1.w);
    }
    // W1: [8][64] -> sW[n][k]
    for (int idx = t; idx < 512; idx += 256) {
        int k = idx >> 6, n = idx & 63;
        sW[n * WP + k] = f2tf32(W1[idx]);
    }
    __syncthreads();

    float acc[8][4];

    // L1: [128,8] @ [8,64]
    mma_layer<1>(sA, sW, acc, slab, gid, tid4);
    store_act_mma(sB, acc, 0.35355339059327373f, slab, gid, tid4);
    __syncthreads();

    // L2
    load_w64(sW, W2, t);
    __syncthreads();
    mma_layer<8>(sB, sW, acc, slab, gid, tid4);
    store_act_mma(sA, acc, 0.125f, slab, gid, tid4);
    __syncthreads();

    // L3
    load_w64(sW, W3, t);
    __syncthreads();
    mma_layer<8>(sA, sW, acc, slab, gid, tid4);
    store_act_mma(sB, acc, 0.125f, slab, gid, tid4);
    __syncthreads();

    // L4: [128,64] @ [64,192] in three 64-col chunks, fp32 out to g_w (CSR order)
#pragma unroll 1
    for (int ch = 0; ch < 3; ++ch) {
        for (int idx = t; idx < 4096; idx += 256) {
            int k = idx >> 6, n = idx & 63;
            sW[n * WP + k] = f2tf32(W4[(size_t)k * 192 + ch * 64 + n]);
        }
        __syncthreads();
        mma_layer<8>(sB, sW, acc, slab, gid, tid4);
#pragma unroll
        for (int nt = 0; nt < 8; ++nt) {
            int col = ch * 64 + nt * 8 + 2 * tid4;
            int r0 = pos_base + slab + gid;
            *(float2*)(g_w + (size_t)r0 * 192 + col) =
                make_float2(acc[nt][0] * 0.125f, acc[nt][1] * 0.125f);
            *(float2*)(g_w + (size_t)(r0 + 8) * 192 + col) =
                make_float2(acc[nt][2] * 0.125f, acc[nt][3] * 0.125f);
        }
        __syncthreads();
    }
}

// ---------------- gather: per-node accumulation, streaming CSR-ordered data ----------------
__global__ __launch_bounds__(256) void k_gather() {
    int t = threadIdx.x;
    int g = t >> 6, c = t & 63;
    int n = blockIdx.x * 4 + g;
    int beg = g_rowstart[n], end = g_rowstart[n + 1];
    float a0 = 0.f, a1 = 0.f, a2 = 0.f, a3 = 0.f, a4 = 0.f,
          a5 = 0.f, a6 = 0.f, a7 = 0.f, a8 = 0.f;
    for (int pos = beg; pos < end; ++pos) {
        int s = g_send[pos];
        float hv = g_h[(size_t)s * 64 + c];
        const float* wp = g_w + (size_t)pos * 192 + c;
        float w0 = wp[0], w1 = wp[64], w2 = wp[128];
        const float* shp = g_sh + (size_t)pos * 12;
        float4 s0 = *(const float4*)shp;
        float4 s1 = *(const float4*)(shp + 4);
        float s8 = shp[8];
        float hw0 = hv * w0, hw1 = hv * w1, hw2 = hv * w2;
        a0 += hw0;
        a1 = fmaf(hw1, s0.y, a1);
        a2 = fmaf(hw1, s0.z, a2);
        a3 = fmaf(hw1, s0.w, a3);
        a4 = fmaf(hw2, s1.x, a4);
        a5 = fmaf(hw2, s1.y, a5);
        a6 = fmaf(hw2, s1.z, a6);
        a7 = fmaf(hw2, s1.w, a7);
        a8 = fmaf(hw2, s8,   a8);
    }
    const float inv_avg = 1.f / 32.f;
    float* ag = g_agg + (size_t)n * 576 + c;
    ag[0]       = a0 * inv_avg;
    ag[64]      = a1 * inv_avg;
    ag[2 * 64]  = a2 * inv_avg;
    ag[3 * 64]  = a3 * inv_avg;
    ag[4 * 64]  = a4 * inv_avg;
    ag[5 * 64]  = a5 * inv_avg;
    ag[6 * 64]  = a6 * inv_avg;
    ag[7 * 64]  = a7 * inv_avg;
    ag[8 * 64]  = a8 * inv_avg;
}

// ---------------- linear_down ----------------
template <int D, int KOFF, int OFF>
__device__ __forceinline__ void down_part(const float* __restrict__ sAg,
                                          const float* __restrict__ wrow,
                                          float* __restrict__ outn, int dch) {
    float acc[D];
#pragma unroll
    for (int m = 0; m < D; ++m) acc[m] = 0.f;
#pragma unroll
    for (int c4 = 0; c4 < 16; ++c4) {
        float4 w = *(const float4*)(wrow + c4 * 4);
#pragma unroll
        for (int m = 0; m < D; ++m) {
            float4 a = *(const float4*)(sAg + (KOFF + m) * 64 + c4 * 4);
            acc[m] += a.x * w.x + a.y * w.y + a.z * w.z + a.w * w.w;
        }
    }
#pragma unroll
    for (int m = 0; m < D; ++m)
        outn[OFF + dch * D + m] = acc[m] * 0.125f;
}

__global__ __launch_bounds__(256) void k_down(const float* __restrict__ Wd,
                                              float* __restrict__ out) {
    extern __shared__ float smf[];
    float* sWt = smf;                 // [192][68]
    float* sAg = smf + 192 * 68;      // [576]
    int t = threadIdx.x;
    for (int idx = t; idx < 3 * 4096; idx += 256) {
        int l = idx >> 12, rem = idx & 4095, c = rem >> 6, dch = rem & 63;
        sWt[(l * 64 + dch) * 68 + c] = Wd[idx];
    }
    __syncthreads();
    int nb = blockIdx.x * 8;
    for (int i = 0; i < 8; ++i) {
        int n = nb + i;
        for (int idx = t; idx < 576; idx += 256)
            sAg[idx] = g_agg[(size_t)n * 576 + idx];
        __syncthreads();
        if (t < 192) {
            int l = t >> 6, dch = t & 63;
            float* outn = out + (size_t)n * 576;
            const float* wrow = sWt + t * 68;
            if (l == 0)      down_part<1, 0, 0>(sAg, wrow, outn, dch);
            else if (l == 1) down_part<3, 1, 64>(sAg, wrow, outn, dch);
            else             down_part<5, 4, 256>(sAg, wrow, outn, dch);
        }
        __syncthreads();
    }
}

// ---------------- launch ----------------
extern "C" void kernel_launch(void* const* d_in, const int* in_sizes, int n_in,
                              void* d_out, int out_size) {
    const float* evec = (const float*)d_in[0];
    const float* nf   = (const float*)d_in[1];
    const float* rad  = (const float*)d_in[2];
    const int* senders   = (const int*)d_in[3];
    const int* receivers = (const int*)d_in[4];
    const float* Wup = (const float*)d_in[5];
    const float* W1  = (const float*)d_in[6];
    const float* W2  = (const float*)d_in[7];
    const float* W3  = (const float*)d_in[8];
    const float* W4  = (const float*)d_in[9];
    const float* Wd  = (const float*)d_in[10];
    float* out = (float*)d_out;

    const int SMEM_EDGE = (2 * 128 * AP + 64 * WP) * 4;   // 95232 B
    const int SMEM_DOWN = (192 * 68 + 9 * 64) * 4;        // 54528 B
    cudaFuncSetAttribute(k_edge, cudaFuncAttributeMaxDynamicSharedMemorySize, SMEM_EDGE);
    cudaFuncSetAttribute(k_down, cudaFuncAttributeMaxDynamicSharedMemorySize, SMEM_DOWN);

    k_zero<<<(N_NODES + 255) / 256, 256>>>();
    k_count<<<N_EDGES / 256, 256>>>(receivers);
    k_scan<<<1, 256>>>();
    k_fill<<<N_EDGES / 256, 256>>>(receivers, senders);
    k_h<<<N_NODES / 4, 256>>>(nf, Wup);
    k_edge<<<N_EDGES / TE, 256, SMEM_EDGE>>>(evec, rad, W1, W2, W3, W4);
    k_gather<<<N_NODES / 4, 256>>>();
    k_down<<<N_NODES / 8, 256, SMEM_DOWN>>>(Wd, out);
}